// round 16
// baseline (speedup 1.0000x reference)
#include <cuda_runtime.h>
#include <stdint.h>

// Fp8Unpadding: gather valid rows out of 256-padded groups.
// inp:       [total_padded, 4096] fp32  (d_in[0])
// m_splits:  [n_groups] int32           (d_in[1])
// out:       [sum(m_splits), 4096] fp32
//
// FINAL — converged at the DRAM roofline. Seven benches of this exact
// kernel: 55.10/55.26/55.46/55.52/56.29/56.83/59.14 us kernel (bench
// 62.2-63.7 us); ~342 MB mixed r/w DRAM traffic at up to 6.19 TB/s
// = ~78% of 8 TB/s spec, the sustained mixed-traffic ceiling on B300.
//   - one block per output row (12166 blocks, 256 threads)
//   - 2 x 256-bit LDG per thread with L2::evict_last (measured -0.7us),
//     front-batched for MLP
//   - 256-bit default-policy stores (all store-side hints measured negative)
//   - 32-bit index math; 8-entry group scan is L1-resident
// Explored and rejected: persistent grid (+4.5us), 128-bit width (neutral),
// __stcs / evict_first stores (+0.8/+1.4us), TMA (LTS path-independent),
// per-group memcpy (graph-illegal), L2 persisting window (device-limit rule).
// Untested-by-design: block-size variants (predicted |delta| < noise floor).

static constexpr int HIDDEN = 4096;
static constexpr int THREADS = 256;
static constexpr int CHUNKS_PER_ROW = HIDDEN / 8;  // 512 x 32B chunks per row

struct alignas(32) f32x8 { uint32_t v[8]; };

__device__ __forceinline__ f32x8 ldg256_evict_last(const f32x8* p) {
    f32x8 r;
    asm volatile("ld.global.L2::evict_last.v8.b32 {%0,%1,%2,%3,%4,%5,%6,%7}, [%8];"
                 : "=r"(r.v[0]), "=r"(r.v[1]), "=r"(r.v[2]), "=r"(r.v[3]),
                   "=r"(r.v[4]), "=r"(r.v[5]), "=r"(r.v[6]), "=r"(r.v[7])
                 : "l"(p));
    return r;
}

__device__ __forceinline__ void stg256(f32x8* p, const f32x8& r) {
    asm volatile("st.global.v8.b32 [%0], {%1,%2,%3,%4,%5,%6,%7,%8};"
                 :: "l"(p),
                    "r"(r.v[0]), "r"(r.v[1]), "r"(r.v[2]), "r"(r.v[3]),
                    "r"(r.v[4]), "r"(r.v[5]), "r"(r.v[6]), "r"(r.v[7])
                 : "memory");
}

__global__ void __launch_bounds__(THREADS, 8)
unpad_gather_kernel(const f32x8* __restrict__ in,
                    const int* __restrict__ m_splits,
                    int n_groups,
                    f32x8* __restrict__ out)
{
    const int row = blockIdx.x;

    // Map output row -> source row. n_groups is tiny (8); L1-resident.
    int cum = 0;      // cumulative valid rows (output offset)
    int pad_off = 0;  // cumulative padded rows (input offset)
    int src_row = 0;
#pragma unroll 1
    for (int g = 0; g < n_groups; ++g) {
        const int m = m_splits[g];
        if (row < cum + m) {
            src_row = pad_off + (row - cum);
            break;
        }
        cum += m;
        pad_off += ((m + 255) >> 8) << 8;  // pad to 256
    }

    const f32x8* __restrict__ src = in  + src_row * CHUNKS_PER_ROW + threadIdx.x;
    f32x8*       __restrict__ dst = out + row     * CHUNKS_PER_ROW + threadIdx.x;

    // Front-batch both 256-bit loads (evict-last), then default stores.
    f32x8 a = ldg256_evict_last(src);
    f32x8 b = ldg256_evict_last(src + THREADS);
    stg256(dst, a);
    stg256(dst + THREADS, b);
}

extern "C" void kernel_launch(void* const* d_in, const int* in_sizes, int n_in,
                              void* d_out, int out_size)
{
    const f32x8* in       = (const f32x8*)d_in[0];
    const int*   m_splits = (const int*)d_in[1];
    const int    n_groups = in_sizes[1];

    f32x8* out = (f32x8*)d_out;
    const int n_rows = out_size / HIDDEN;  // total valid rows

    unpad_gather_kernel<<<n_rows, THREADS>>>(in, m_splits, n_groups, out);
}

// round 17
// speedup vs baseline: 1.0248x; 1.0248x over previous
#include <cuda_runtime.h>
#include <stdint.h>

// Fp8Unpadding: gather valid rows out of 256-padded groups.
// inp:       [total_padded, 4096] fp32  (d_in[0])
// m_splits:  [n_groups] int32           (d_in[1])
// out:       [sum(m_splits), 4096] fp32
//
// FINAL — converged at the DRAM roofline. Eight benches of this exact
// kernel: 55.10-59.14 us kernel time (median ~55.5), bench 62.2-63.7 us;
// ~342 MB mixed r/w DRAM traffic at up to 6.19 TB/s = ~78% of 8 TB/s
// spec, the sustained mixed-traffic ceiling on B300.
//   - one block per output row (12166 blocks, 256 threads)
//   - 2 x 256-bit LDG per thread with L2::evict_last (measured -0.7us),
//     front-batched for MLP
//   - 256-bit default-policy stores (all store-side hints measured negative)
//   - 32-bit index math; 8-entry group scan is L1-resident
// Explored and rejected: persistent grid (+4.5us), 128-bit width (neutral),
// __stcs / evict_first stores (+0.8/+1.4us), TMA (LTS path-independent),
// per-group memcpy (graph-illegal), L2 persisting window (device-limit rule).
// Untested-by-design: block-size variants (predicted |delta| < noise floor).

static constexpr int HIDDEN = 4096;
static constexpr int THREADS = 256;
static constexpr int CHUNKS_PER_ROW = HIDDEN / 8;  // 512 x 32B chunks per row

struct alignas(32) f32x8 { uint32_t v[8]; };

__device__ __forceinline__ f32x8 ldg256_evict_last(const f32x8* p) {
    f32x8 r;
    asm volatile("ld.global.L2::evict_last.v8.b32 {%0,%1,%2,%3,%4,%5,%6,%7}, [%8];"
                 : "=r"(r.v[0]), "=r"(r.v[1]), "=r"(r.v[2]), "=r"(r.v[3]),
                   "=r"(r.v[4]), "=r"(r.v[5]), "=r"(r.v[6]), "=r"(r.v[7])
                 : "l"(p));
    return r;
}

__device__ __forceinline__ void stg256(f32x8* p, const f32x8& r) {
    asm volatile("st.global.v8.b32 [%0], {%1,%2,%3,%4,%5,%6,%7,%8};"
                 :: "l"(p),
                    "r"(r.v[0]), "r"(r.v[1]), "r"(r.v[2]), "r"(r.v[3]),
                    "r"(r.v[4]), "r"(r.v[5]), "r"(r.v[6]), "r"(r.v[7])
                 : "memory");
}

__global__ void __launch_bounds__(THREADS, 8)
unpad_gather_kernel(const f32x8* __restrict__ in,
                    const int* __restrict__ m_splits,
                    int n_groups,
                    f32x8* __restrict__ out)
{
    const int row = blockIdx.x;

    // Map output row -> source row. n_groups is tiny (8); L1-resident.
    int cum = 0;      // cumulative valid rows (output offset)
    int pad_off = 0;  // cumulative padded rows (input offset)
    int src_row = 0;
#pragma unroll 1
    for (int g = 0; g < n_groups; ++g) {
        const int m = m_splits[g];
        if (row < cum + m) {
            src_row = pad_off + (row - cum);
            break;
        }
        cum += m;
        pad_off += ((m + 255) >> 8) << 8;  // pad to 256
    }

    const f32x8* __restrict__ src = in  + src_row * CHUNKS_PER_ROW + threadIdx.x;
    f32x8*       __restrict__ dst = out + row     * CHUNKS_PER_ROW + threadIdx.x;

    // Front-batch both 256-bit loads (evict-last), then default stores.
    f32x8 a = ldg256_evict_last(src);
    f32x8 b = ldg256_evict_last(src + THREADS);
    stg256(dst, a);
    stg256(dst + THREADS, b);
}

extern "C" void kernel_launch(void* const* d_in, const int* in_sizes, int n_in,
                              void* d_out, int out_size)
{
    const f32x8* in       = (const f32x8*)d_in[0];
    const int*   m_splits = (const int*)d_in[1];
    const int    n_groups = in_sizes[1];

    f32x8* out = (f32x8*)d_out;
    const int n_rows = out_size / HIDDEN;  // total valid rows

    unpad_gather_kernel<<<n_rows, THREADS>>>(in, m_splits, n_groups, out);
}